// round 7
// baseline (speedup 1.0000x reference)
#include <cuda_runtime.h>
#include <math.h>
#include <float.h>

#define DD   64
#define TT   4096
#define NN   20000
#define MM   24096     // TT + NN
#define EE   100000
#define RR   50
#define TOKN 768

#define GRIDN 148
#define NTHREADS (GRIDN * 256)

// ---------------- scratch (device globals; no allocation allowed) ----------------
__device__ __align__(16) float g_x[MM*DD];
__device__ __align__(16) float g_h[MM*DD];
__device__ __align__(16) float g_fx[MM*DD];
__device__ __align__(16) float g_aggr[MM*DD];
__device__ __align__(16) float g_W[RR*DD*DD];
__device__ __align__(16) float g_u1[RR*DD];
__device__ __align__(16) float g_u2[RR*DD];
__device__ int   g_rel[EE];
__device__ float g_mask[EE];
__device__ float g_p[MM];
__device__ float g_logit[EE];
__device__ float g_max1, g_sum1, g_max2, g_sum2;
__device__ float g_kge;
__device__ float g_nt;
__device__ unsigned long long g_bar;   // monotonic grid-barrier ticket counter

// ---------------- helpers ----------------
__device__ __forceinline__ void atomicMaxF(float* addr, float v) {
    int old = __float_as_int(*addr);
    while (__int_as_float(old) < v) {
        int prev = atomicCAS((int*)addr, old, __float_as_int(v));
        if (prev == old) break;
        old = prev;
    }
}

// monotonic-ticket grid barrier: requires exactly GRIDN co-resident blocks.
__device__ __forceinline__ void gridBarrier() {
    __syncthreads();
    __threadfence();
    if (threadIdx.x == 0) {
        unsigned long long t = atomicAdd(&g_bar, 1ULL);
        unsigned long long tgt = (t / GRIDN + 1ULL) * GRIDN;
        while (*(volatile unsigned long long*)&g_bar < tgt) { }
        __threadfence();
    }
    __syncthreads();
}

__device__ __forceinline__ unsigned long long fmaf2(unsigned long long a,
                                                    unsigned long long b,
                                                    unsigned long long c) {
    unsigned long long d;
    asm("fma.rn.f32x2 %0, %1, %2, %3;" : "=l"(d) : "l"(a), "l"(b), "l"(c));
    return d;
}

__device__ __forceinline__ float2 u2f(unsigned long long v) {
    float2 r;
    asm("mov.b64 {%0, %1}, %2;" : "=f"(r.x), "=f"(r.y) : "l"(v));
    return r;
}

// ================= packed-f32x2 GEMM: C[m,n] = A[m,:K] @ B[:K,n] =================
#define LDA 132
#define LDB 136

template<int RELU, int HASADD, int ATOMIC, int ZEROADD>
__global__ void __launch_bounds__(256, 2)
gemm_f2(const float* __restrict__ A, const float* __restrict__ B,
        const float* __restrict__ bias, float* __restrict__ addsrc,
        float* __restrict__ C, int Mrows, int N, int K, int kPerZ)
{
    __shared__ float shA[32*LDA];
    __shared__ float shB[32*LDB];
    int tid  = threadIdx.x;
    int row0 = blockIdx.y * 128;
    int col0 = blockIdx.x * 64;
    int ctid = tid & 15;
    int rtid = tid >> 4;
    int c0 = ctid * 4;
    int r0 = rtid * 8;

    unsigned long long acc[4][4];
    #pragma unroll
    for (int i = 0; i < 4; i++)
        #pragma unroll
        for (int j = 0; j < 4; j++) acc[i][j] = 0ULL;

    int kb = blockIdx.z * kPerZ;
    for (int kc = kb; kc < kb + kPerZ; kc += 32) {
        #pragma unroll
        for (int i = 0; i < 4; i++) {
            int lin = tid + i * 256;
            int row = lin & 127;
            int kq  = lin >> 7;
            float4 v = make_float4(0.f, 0.f, 0.f, 0.f);
            if (row0 + row < Mrows)
                v = *(const float4*)&A[(long)(row0 + row) * K + kc + kq * 4];
            shA[(kq*4 + 0)*LDA + row] = v.x;
            shA[(kq*4 + 1)*LDA + row] = v.y;
            shA[(kq*4 + 2)*LDA + row] = v.z;
            shA[(kq*4 + 3)*LDA + row] = v.w;
        }
        #pragma unroll
        for (int i = 0; i < 2; i++) {
            int lin = tid + i * 256;
            int c4 = lin & 15;
            int k  = lin >> 4;
            float4 v = *(const float4*)&B[(long)(kc + k) * N + col0 + c4 * 4];
            *(float4*)&shB[k*LDB + c4*8]     = make_float4(v.x, v.x, v.y, v.y);
            *(float4*)&shB[k*LDB + c4*8 + 4] = make_float4(v.z, v.z, v.w, v.w);
        }
        __syncthreads();

        #pragma unroll
        for (int k = 0; k < 32; k++) {
            ulonglong2 a01 = *(const ulonglong2*)&shA[k*LDA + r0];
            ulonglong2 a23 = *(const ulonglong2*)&shA[k*LDA + r0 + 4];
            ulonglong2 b01 = *(const ulonglong2*)&shB[k*LDB + c0*2];
            ulonglong2 b23 = *(const ulonglong2*)&shB[k*LDB + c0*2 + 4];
            acc[0][0] = fmaf2(a01.x, b01.x, acc[0][0]);
            acc[0][1] = fmaf2(a01.x, b01.y, acc[0][1]);
            acc[0][2] = fmaf2(a01.x, b23.x, acc[0][2]);
            acc[0][3] = fmaf2(a01.x, b23.y, acc[0][3]);
            acc[1][0] = fmaf2(a01.y, b01.x, acc[1][0]);
            acc[1][1] = fmaf2(a01.y, b01.y, acc[1][1]);
            acc[1][2] = fmaf2(a01.y, b23.x, acc[1][2]);
            acc[1][3] = fmaf2(a01.y, b23.y, acc[1][3]);
            acc[2][0] = fmaf2(a23.x, b01.x, acc[2][0]);
            acc[2][1] = fmaf2(a23.x, b01.y, acc[2][1]);
            acc[2][2] = fmaf2(a23.x, b23.x, acc[2][2]);
            acc[2][3] = fmaf2(a23.x, b23.y, acc[2][3]);
            acc[3][0] = fmaf2(a23.y, b01.x, acc[3][0]);
            acc[3][1] = fmaf2(a23.y, b01.y, acc[3][1]);
            acc[3][2] = fmaf2(a23.y, b23.x, acc[3][2]);
            acc[3][3] = fmaf2(a23.y, b23.y, acc[3][3]);
        }
        __syncthreads();
    }

    float4 bv = *(const float4*)&bias[col0 + c0];
    bool addbias = !ATOMIC || (blockIdx.z == 0);

    #pragma unroll
    for (int rp = 0; rp < 4; rp++) {
        float2 f0 = u2f(acc[rp][0]);
        float2 f1 = u2f(acc[rp][1]);
        float2 f2 = u2f(acc[rp][2]);
        float2 f3 = u2f(acc[rp][3]);
        float4 vlo = make_float4(f0.x, f1.x, f2.x, f3.x);
        float4 vhi = make_float4(f0.y, f1.y, f2.y, f3.y);
        #pragma unroll
        for (int half = 0; half < 2; half++) {
            int row = row0 + r0 + rp*2 + half;
            if (row >= Mrows) continue;
            float4 v = half ? vhi : vlo;
            if (addbias) { v.x += bv.x; v.y += bv.y; v.z += bv.z; v.w += bv.w; }
            if (HASADD) {
                float4 ad = *(float4*)&addsrc[(long)row * N + col0 + c0];
                v.x += ad.x; v.y += ad.y; v.z += ad.z; v.w += ad.w;
                if (ZEROADD)
                    *(float4*)&addsrc[(long)row * N + col0 + c0] =
                        make_float4(0.f, 0.f, 0.f, 0.f);
            }
            if (RELU) {
                v.x = fmaxf(v.x, 0.f); v.y = fmaxf(v.y, 0.f);
                v.z = fmaxf(v.z, 0.f); v.w = fmaxf(v.w, 0.f);
            }
            if (ATOMIC) {
                float* cp = &C[(long)row * N + col0 + c0];
                atomicAdd(cp + 0, v.x); atomicAdd(cp + 1, v.y);
                atomicAdd(cp + 2, v.z); atomicAdd(cp + 3, v.w);
            } else {
                *(float4*)&C[(long)row * N + col0 + c0] = v;
            }
        }
    }
}

// ---------------- init: zero tok x + aggr, gather kg nodes, reset scalars ----------------
__global__ void k_init(const int* __restrict__ node_ids, const float* __restrict__ kg_emb)
{
    int idx = blockIdx.x * blockDim.x + threadIdx.x;   // float4 units
    float4 z = make_float4(0.f, 0.f, 0.f, 0.f);
    if (idx < MM*16) ((float4*)g_aggr)[idx] = z;
    if (idx < TT*16) ((float4*)g_x)[idx] = z;
    if (idx < NN*16) {
        int n = idx >> 4, q = idx & 15;
        ((float4*)g_x)[(long)(TT + n)*16 + q] =
            ((const float4*)kg_emb)[(long)node_ids[n]*16 + q];
    }
    if (idx == 0) {
        g_kge = 0.f; g_nt = 0.f;
        g_max1 = -FLT_MAX; g_sum1 = 0.f;
        g_max2 = -FLT_MAX; g_sum2 = 0.f;
    }
}

// ---------------- edge prep: relation id + mask (smem-staged); u tables ----------------
#define EPB 128
#define EB  ((EE + EPB - 1) / EPB)
__global__ void k_edgeprep(const float* __restrict__ ea,
                           const float* __restrict__ att1_w,
                           const float* __restrict__ att2_w)
{
    int b = blockIdx.x;
    if (b < EB) {
        __shared__ float sm[EPB * RR];
        int e0 = b * EPB;
        int cnt = min(EPB, EE - e0);
        int total = cnt * RR;
        const float* base = ea + (long)e0 * RR;
        for (int i = threadIdx.x; i < total; i += 256) sm[i] = base[i];
        __syncthreads();
        int el = threadIdx.x;
        if (el < cnt) {
            const float* row = sm + el * RR;
            float acc = 0.f;
            #pragma unroll
            for (int r = 1; r < RR; r++) acc += row[r] * (float)r;
            g_rel[e0 + el] = (int)(acc + 0.5f);
            g_mask[e0 + el] = (row[47] + row[48] + row[49] == 0.f) ? 1.f : 0.f;
        }
    } else {
        int idx = (b - EB) * 256 + threadIdx.x;
        if (idx >= RR*DD) return;
        int rel = idx >> 6, d = idx & 63;
        const float4* wrow = (const float4*)(g_W + (long)rel*4096 + d*64);
        const float4* w1 = (const float4*)(att1_w + 64);
        const float4* w2 = (const float4*)(att2_w + 64);
        float a1 = 0.f, a2 = 0.f;
        #pragma unroll
        for (int o = 0; o < 16; o++) {
            float4 w = wrow[o];
            float4 v1 = w1[o], v2 = w2[o];
            a1 += w.x*v1.x + w.y*v1.y + w.z*v1.z + w.w*v1.w;
            a2 += w.x*v2.x + w.y*v2.y + w.z*v2.z + w.w*v2.w;
        }
        g_u1[idx] = a1; g_u2[idx] = a2;
    }
}

// ================ persistent per-layer edge phase: p -> logit/max -> exp/sum -> scatter =
__global__ void __launch_bounds__(256, 1)
k_edge(const float* __restrict__ x, const float* __restrict__ u,
       const int* __restrict__ src, const int* __restrict__ dst,
       const float* __restrict__ att_w, const float* __restrict__ att_b,
       float* __restrict__ pmax, float* __restrict__ psum)
{
    __shared__ float sm[256];
    int gtid = blockIdx.x * 256 + threadIdx.x;

    // ---- phase P: p[n] = att_b + x[n] . att_w[0:64] ----
    float attb = att_b[0];
    for (int n = gtid; n < MM; n += NTHREADS) {
        float acc = attb;
        const float4* xr = (const float4*)(x + (long)n * DD);
        const float4* wr = (const float4*)att_w;
        #pragma unroll
        for (int k = 0; k < 16; k++) {
            float4 a = xr[k], w = wr[k];
            acc += a.x*w.x + a.y*w.y + a.z*w.z + a.w*w.w;
        }
        g_p[n] = acc;
    }
    gridBarrier();

    // ---- phase A: logits + global max ----
    float lmax = -FLT_MAX;
    for (int e = gtid; e < EE; e += NTHREADS) {
        float acc = g_p[dst[e]];
        const float4* xr = (const float4*)(x + (long)src[e] * DD);
        const float4* ur = (const float4*)(u + g_rel[e] * DD);
        #pragma unroll
        for (int k = 0; k < 16; k++) {
            float4 a = xr[k], w = ur[k];
            acc += a.x*w.x + a.y*w.y + a.z*w.z + a.w*w.w;
        }
        g_logit[e] = acc;
        lmax = fmaxf(lmax, acc);
    }
    sm[threadIdx.x] = lmax; __syncthreads();
    for (int s = 128; s > 0; s >>= 1) {
        if (threadIdx.x < s) sm[threadIdx.x] = fmaxf(sm[threadIdx.x], sm[threadIdx.x + s]);
        __syncthreads();
    }
    if (threadIdx.x == 0) atomicMaxF(pmax, sm[0]);
    gridBarrier();

    // ---- phase B: exp(logit - max) + global sum ----
    float gmax = *pmax;
    float lsum = 0.f;
    for (int e = gtid; e < EE; e += NTHREADS) {
        float v = __expf(g_logit[e] - gmax);
        g_logit[e] = v;
        lsum += v;
    }
    sm[threadIdx.x] = lsum; __syncthreads();
    for (int s = 128; s > 0; s >>= 1) {
        if (threadIdx.x < s) sm[threadIdx.x] += sm[threadIdx.x + s];
        __syncthreads();
    }
    if (threadIdx.x == 0) atomicAdd(psum, sm[0]);
    gridBarrier();

    // ---- phase C: scatter aggr[dst] += x[src] * alpha (scalar atomics) ----
    float inv = 1.f / *psum;
    for (int idx = gtid; idx < EE * 16; idx += NTHREADS) {
        int e = idx >> 4, q = idx & 15;
        float a = g_logit[e] * inv;
        float4 v = *(const float4*)&x[(long)src[e]*DD + q*4];
        float* ap = &g_aggr[(long)dst[e]*DD + q*4];
        atomicAdd(ap + 0, v.x * a);
        atomicAdd(ap + 1, v.y * a);
        atomicAdd(ap + 2, v.z * a);
        atomicAdd(ap + 3, v.w * a);
    }
}

// ---------------- fused losses: kge (blocks < KB) + nt (rest) ----------------
#define KB 512
__global__ void k_loss(const int* __restrict__ src, const int* __restrict__ dst,
                       const float* __restrict__ rel_emb,
                       const int* __restrict__ labels,
                       const float* __restrict__ w_nt, const float* __restrict__ b_nt)
{
    __shared__ float sm[256];
    if (blockIdx.x < KB) {
        float acc = 0.f;
        for (long idx = (long)blockIdx.x * 256 + threadIdx.x; idx < (long)EE * 16;
             idx += (long)KB * 256) {
            int e = (int)(idx >> 4), q = (int)(idx & 15);
            if (g_mask[e] != 0.f) {
                float4 a = *(const float4*)&g_fx[(long)src[e]*DD + q*4];
                float4 b = *(const float4*)&g_fx[(long)dst[e]*DD + q*4];
                float4 r = *(const float4*)&rel_emb[g_rel[e]*DD + q*4];
                float dx = a.x + r.x - b.x;
                float dy = a.y + r.y - b.y;
                float dz = a.z + r.z - b.z;
                float dw = a.w + r.w - b.w;
                acc += dx*dx + dy*dy + dz*dz + dw*dw;
            }
        }
        sm[threadIdx.x] = acc; __syncthreads();
        for (int s = 128; s > 0; s >>= 1) {
            if (threadIdx.x < s) sm[threadIdx.x] += sm[threadIdx.x + s];
            __syncthreads();
        }
        if (threadIdx.x == 0) atomicAdd(&g_kge, sm[0]);
    } else {
        int n = (blockIdx.x - KB) * 256 + threadIdx.x;
        float loss = 0.f;
        if (n < MM) {
            const float* xr = g_fx + (long)n * DD;
            float z0 = b_nt[0], z1 = b_nt[1], z2 = b_nt[2];
            #pragma unroll 16
            for (int k = 0; k < DD; k++) {
                float v = xr[k];
                z0 += v * w_nt[k*3 + 0];
                z1 += v * w_nt[k*3 + 1];
                z2 += v * w_nt[k*3 + 2];
            }
            float mx  = fmaxf(z0, fmaxf(z1, z2));
            float lse = mx + logf(expf(z0 - mx) + expf(z1 - mx) + expf(z2 - mx));
            int lab = labels[n];
            float zl = (lab == 0) ? z0 : ((lab == 1) ? z1 : z2);
            loss = lse - zl;
        }
        sm[threadIdx.x] = loss; __syncthreads();
        for (int s = 128; s > 0; s >>= 1) {
            if (threadIdx.x < s) sm[threadIdx.x] += sm[threadIdx.x + s];
            __syncthreads();
        }
        if (threadIdx.x == 0) atomicAdd(&g_nt, sm[0]);
    }
}

// ---------------- write loss scalars ----------------
__global__ void k_finalize(float* __restrict__ out, long off)
{
    out[off]     = g_kge / (float)((long)EE * DD);
    out[off + 1] = g_nt / (float)MM;
}

// =====================================================================================
extern "C" void kernel_launch(void* const* d_in, const int* in_sizes, int n_in,
                              void* d_out, int out_size)
{
    const int*   node_ids   = (const int*)  d_in[0];
    const int*   edge_index = (const int*)  d_in[1];
    const float* edge_attr  = (const float*)d_in[2];
    const float* tokemb     = (const float*)d_in[3];
    const int*   labels     = (const int*)  d_in[4];
    const float* kg_emb     = (const float*)d_in[5];
    const float* rel_emb    = (const float*)d_in[6];
    const float* w_e2       = (const float*)d_in[7];
    const float* b_e2       = (const float*)d_in[8];
    const float* att1_w     = (const float*)d_in[9];
    const float* att1_b     = (const float*)d_in[10];
    const float* root1      = (const float*)d_in[11];
    const float* bias1      = (const float*)d_in[12];
    const float* att2_w     = (const float*)d_in[13];
    const float* att2_b     = (const float*)d_in[14];
    const float* root2      = (const float*)d_in[15];
    const float* bias2      = (const float*)d_in[16];
    const float* w_lin1     = (const float*)d_in[17];
    const float* b_lin1     = (const float*)d_in[18];
    const float* w_lin2     = (const float*)d_in[19];
    const float* b_lin2     = (const float*)d_in[20];
    const float* w_nt       = (const float*)d_in[21];
    const float* b_nt       = (const float*)d_in[22];
    float* out = (float*)d_out;

    const int* src = edge_index;        // edge_index[0, :]
    const int* dst = edge_index + EE;   // edge_index[1, :]

    void *px_, *ph_, *pfx_, *paggr_, *pW_, *pu1_, *pu2_;
    void *pm1_, *ps1_, *pm2_, *ps2_;
    cudaGetSymbolAddress(&px_,    g_x);
    cudaGetSymbolAddress(&ph_,    g_h);
    cudaGetSymbolAddress(&pfx_,   g_fx);
    cudaGetSymbolAddress(&paggr_, g_aggr);
    cudaGetSymbolAddress(&pu1_,   g_u1);
    cudaGetSymbolAddress(&pu2_,   g_u2);
    cudaGetSymbolAddress(&pW_,    g_W);
    cudaGetSymbolAddress(&pm1_,   g_max1);
    cudaGetSymbolAddress(&ps1_,   g_sum1);
    cudaGetSymbolAddress(&pm2_,   g_max2);
    cudaGetSymbolAddress(&ps2_,   g_sum2);
    float* px    = (float*)px_;
    float* ph    = (float*)ph_;
    float* pfx   = (float*)pfx_;
    float* paggr = (float*)paggr_;
    float* pu1   = (float*)pu1_;
    float* pu2   = (float*)pu2_;
    float* pW    = (float*)pW_;

    // ---- init scratch ----
    k_init<<<(MM*16 + 255)/256, 256>>>(node_ids, kg_emb);

    // ---- tok = token_embeddings @ w_lin1 + b_lin1 (split-K over z, atomic) ----
    {
        dim3 grid(1, (TT + 127)/128, 8);
        gemm_f2<0,0,1,0><<<grid, 256>>>(tokemb, w_lin1, b_lin1, nullptr, px, TT, DD, TOKN, 96);
    }

    // ---- W[r] = relu(rel_emb @ w_e2 + b_e2) as GEMM [50,64]x[64,4096] ----
    {
        dim3 grid(4096/64, 1, 1);
        gemm_f2<1,0,0,0><<<grid, 256>>>(rel_emb, w_e2, b_e2, nullptr, pW, RR, 4096, DD, DD);
    }
    k_edgeprep<<<EB + (RR*DD + 255)/256, 256>>>(edge_attr, att1_w, att2_w);

    // ---- layer 1: persistent edge phase, then GEMM (relu, +aggr, re-zero aggr) ----
    k_edge<<<GRIDN, 256>>>(px, pu1, src, dst, att1_w, att1_b, (float*)pm1_, (float*)ps1_);
    {
        dim3 grid(1, (MM + 127)/128, 1);
        gemm_f2<1,1,0,1><<<grid, 256>>>(px, root1, bias1, paggr, ph, MM, DD, DD, DD);
    }

    // ---- layer 2 ----
    k_edge<<<GRIDN, 256>>>(ph, pu2, src, dst, att2_w, att2_b, (float*)pm2_, (float*)ps2_);
    {
        dim3 grid(1, (MM + 127)/128, 1);
        gemm_f2<0,1,0,0><<<grid, 256>>>(ph, root2, bias2, paggr, pfx, MM, DD, DD, DD);
    }

    // ---- losses (fused) ----
    k_loss<<<KB + (MM + 255)/256, 256>>>(src, dst, rel_emb, labels, w_nt, b_nt);

    // ---- final outputs: final_x @ w_lin2 + b_lin2 ----
    {
        dim3 grid(TOKN/64, (MM + 127)/128, 1);
        gemm_f2<0,0,0,0><<<grid, 256>>>(pfx, w_lin2, b_lin2, nullptr, out, MM, TOKN, DD, DD);
    }

    // ---- loss scalars at the tail of d_out ----
    k_finalize<<<1, 1>>>(out, (long)out_size - 2);
}

// round 8
// speedup vs baseline: 1.0774x; 1.0774x over previous
#include <cuda_runtime.h>
#include <math.h>
#include <float.h>

#define DD   64
#define TT   4096
#define NN   20000
#define MM   24096     // TT + NN
#define EE   100000
#define RR   50
#define TOKN 768

// ---------------- scratch (device globals; no allocation allowed) ----------------
__device__ __align__(16) float g_x[MM*DD];
__device__ __align__(16) float g_h[MM*DD];
__device__ __align__(16) float g_fx[MM*DD];
__device__ __align__(16) float g_aggr[MM*DD];
__device__ __align__(16) float g_W[RR*DD*DD];
__device__ __align__(16) float g_u1[RR*DD];
__device__ __align__(16) float g_u2[RR*DD];
__device__ int   g_rel[EE];
__device__ float g_mask[EE];
__device__ float g_p[MM];
__device__ float g_logit[EE];
__device__ float g_sum1, g_sum2;
__device__ float g_kge;
__device__ float g_nt;

// ---------------- helpers ----------------
__device__ __forceinline__ unsigned long long fmaf2(unsigned long long a,
                                                    unsigned long long b,
                                                    unsigned long long c) {
    unsigned long long d;
    asm("fma.rn.f32x2 %0, %1, %2, %3;" : "=l"(d) : "l"(a), "l"(b), "l"(c));
    return d;
}

__device__ __forceinline__ float2 u2f(unsigned long long v) {
    float2 r;
    asm("mov.b64 {%0, %1}, %2;" : "=f"(r.x), "=f"(r.y) : "l"(v));
    return r;
}

// ================= packed-f32x2 GEMM: C[m,n] = A[m,:K] @ B[:K,n] =================
// BM=128, BN=64, BK=32, 256 threads, per-thread 8 rows x 4 cols via 4x4 f32x2 accs.
#define LDA 132
#define LDB 136

template<int RELU, int HASADD, int ATOMIC, int ZEROADD>
__global__ void __launch_bounds__(256, 2)
gemm_f2(const float* __restrict__ A, const float* __restrict__ B,
        const float* __restrict__ bias, float* __restrict__ addsrc,
        float* __restrict__ C, int Mrows, int N, int K, int kPerZ)
{
    __shared__ float shA[32*LDA];
    __shared__ float shB[32*LDB];
    int tid  = threadIdx.x;
    int row0 = blockIdx.y * 128;
    int col0 = blockIdx.x * 64;
    int ctid = tid & 15;
    int rtid = tid >> 4;
    int c0 = ctid * 4;
    int r0 = rtid * 8;

    unsigned long long acc[4][4];
    #pragma unroll
    for (int i = 0; i < 4; i++)
        #pragma unroll
        for (int j = 0; j < 4; j++) acc[i][j] = 0ULL;

    int kb = blockIdx.z * kPerZ;
    for (int kc = kb; kc < kb + kPerZ; kc += 32) {
        #pragma unroll
        for (int i = 0; i < 4; i++) {
            int lin = tid + i * 256;
            int row = lin & 127;
            int kq  = lin >> 7;
            float4 v = make_float4(0.f, 0.f, 0.f, 0.f);
            if (row0 + row < Mrows)
                v = *(const float4*)&A[(long)(row0 + row) * K + kc + kq * 4];
            shA[(kq*4 + 0)*LDA + row] = v.x;
            shA[(kq*4 + 1)*LDA + row] = v.y;
            shA[(kq*4 + 2)*LDA + row] = v.z;
            shA[(kq*4 + 3)*LDA + row] = v.w;
        }
        #pragma unroll
        for (int i = 0; i < 2; i++) {
            int lin = tid + i * 256;
            int c4 = lin & 15;
            int k  = lin >> 4;
            float4 v = *(const float4*)&B[(long)(kc + k) * N + col0 + c4 * 4];
            *(float4*)&shB[k*LDB + c4*8]     = make_float4(v.x, v.x, v.y, v.y);
            *(float4*)&shB[k*LDB + c4*8 + 4] = make_float4(v.z, v.z, v.w, v.w);
        }
        __syncthreads();

        #pragma unroll
        for (int k = 0; k < 32; k++) {
            ulonglong2 a01 = *(const ulonglong2*)&shA[k*LDA + r0];
            ulonglong2 a23 = *(const ulonglong2*)&shA[k*LDA + r0 + 4];
            ulonglong2 b01 = *(const ulonglong2*)&shB[k*LDB + c0*2];
            ulonglong2 b23 = *(const ulonglong2*)&shB[k*LDB + c0*2 + 4];
            acc[0][0] = fmaf2(a01.x, b01.x, acc[0][0]);
            acc[0][1] = fmaf2(a01.x, b01.y, acc[0][1]);
            acc[0][2] = fmaf2(a01.x, b23.x, acc[0][2]);
            acc[0][3] = fmaf2(a01.x, b23.y, acc[0][3]);
            acc[1][0] = fmaf2(a01.y, b01.x, acc[1][0]);
            acc[1][1] = fmaf2(a01.y, b01.y, acc[1][1]);
            acc[1][2] = fmaf2(a01.y, b23.x, acc[1][2]);
            acc[1][3] = fmaf2(a01.y, b23.y, acc[1][3]);
            acc[2][0] = fmaf2(a23.x, b01.x, acc[2][0]);
            acc[2][1] = fmaf2(a23.x, b01.y, acc[2][1]);
            acc[2][2] = fmaf2(a23.x, b23.x, acc[2][2]);
            acc[2][3] = fmaf2(a23.x, b23.y, acc[2][3]);
            acc[3][0] = fmaf2(a23.y, b01.x, acc[3][0]);
            acc[3][1] = fmaf2(a23.y, b01.y, acc[3][1]);
            acc[3][2] = fmaf2(a23.y, b23.x, acc[3][2]);
            acc[3][3] = fmaf2(a23.y, b23.y, acc[3][3]);
        }
        __syncthreads();
    }

    float4 bv = *(const float4*)&bias[col0 + c0];
    bool addbias = !ATOMIC || (blockIdx.z == 0);

    #pragma unroll
    for (int rp = 0; rp < 4; rp++) {
        float2 f0 = u2f(acc[rp][0]);
        float2 f1 = u2f(acc[rp][1]);
        float2 f2 = u2f(acc[rp][2]);
        float2 f3 = u2f(acc[rp][3]);
        float4 vlo = make_float4(f0.x, f1.x, f2.x, f3.x);
        float4 vhi = make_float4(f0.y, f1.y, f2.y, f3.y);
        #pragma unroll
        for (int half = 0; half < 2; half++) {
            int row = row0 + r0 + rp*2 + half;
            if (row >= Mrows) continue;
            float4 v = half ? vhi : vlo;
            if (addbias) { v.x += bv.x; v.y += bv.y; v.z += bv.z; v.w += bv.w; }
            if (HASADD) {
                float4 ad = *(float4*)&addsrc[(long)row * N + col0 + c0];
                v.x += ad.x; v.y += ad.y; v.z += ad.z; v.w += ad.w;
                if (ZEROADD)
                    *(float4*)&addsrc[(long)row * N + col0 + c0] =
                        make_float4(0.f, 0.f, 0.f, 0.f);
            }
            if (RELU) {
                v.x = fmaxf(v.x, 0.f); v.y = fmaxf(v.y, 0.f);
                v.z = fmaxf(v.z, 0.f); v.w = fmaxf(v.w, 0.f);
            }
            if (ATOMIC) {
                float* cp = &C[(long)row * N + col0 + c0];
                atomicAdd(cp + 0, v.x); atomicAdd(cp + 1, v.y);
                atomicAdd(cp + 2, v.z); atomicAdd(cp + 3, v.w);
            } else {
                *(float4*)&C[(long)row * N + col0 + c0] = v;
            }
        }
    }
}

// ---------------- init: zero aggr + tok region of x, gather kg nodes, reset scalars ----
__global__ void k_init(const int* __restrict__ node_ids, const float* __restrict__ kg_emb)
{
    int idx = blockIdx.x * blockDim.x + threadIdx.x;   // float4 units
    float4 z = make_float4(0.f, 0.f, 0.f, 0.f);
    if (idx < MM*16) ((float4*)g_aggr)[idx] = z;
    if (idx < TT*16) ((float4*)g_x)[idx] = z;
    if (idx < NN*16) {
        int n = idx >> 4, q = idx & 15;
        ((float4*)g_x)[(long)(TT + n)*16 + q] =
            ((const float4*)kg_emb)[(long)node_ids[n]*16 + q];
    }
    if (idx == 0) { g_kge = 0.f; g_nt = 0.f; g_sum1 = 0.f; g_sum2 = 0.f; }
}

// ---------------- edge prep: relation id + mask (float4 smem staging); u tables -------
#define EPB 128
#define EB  ((EE + EPB - 1) / EPB)
__global__ void k_edgeprep(const float* __restrict__ ea,
                           const float* __restrict__ att1_w,
                           const float* __restrict__ att2_w)
{
    int b = blockIdx.x;
    if (b < EB) {
        __shared__ float sm[EPB * RR];
        int e0 = b * EPB;
        int cnt = min(EPB, EE - e0);
        int total4 = (cnt * RR) >> 2;      // always divisible by 4 (cnt multiple of 32)
        // base byte offset e0*200 is divisible by 16 (e0 multiple of 128)
        const float4* base4 = (const float4*)(ea + (long)e0 * RR);
        float4* sm4 = (float4*)sm;
        for (int i = threadIdx.x; i < total4; i += 256) sm4[i] = base4[i];
        __syncthreads();
        int el = threadIdx.x;
        if (el < cnt) {
            const float* row = sm + el * RR;
            float acc = 0.f;
            #pragma unroll
            for (int r = 1; r < RR; r++) acc += row[r] * (float)r;
            g_rel[e0 + el] = (int)(acc + 0.5f);
            g_mask[e0 + el] = (row[47] + row[48] + row[49] == 0.f) ? 1.f : 0.f;
        }
    } else {
        int idx = (b - EB) * 256 + threadIdx.x;
        if (idx >= RR*DD) return;
        int rel = idx >> 6, d = idx & 63;
        const float4* wrow = (const float4*)(g_W + (long)rel*4096 + d*64);
        const float4* w1 = (const float4*)(att1_w + 64);
        const float4* w2 = (const float4*)(att2_w + 64);
        float a1 = 0.f, a2 = 0.f;
        #pragma unroll
        for (int o = 0; o < 16; o++) {
            float4 w = wrow[o];
            float4 v1 = w1[o], v2 = w2[o];
            a1 += w.x*v1.x + w.y*v1.y + w.z*v1.z + w.w*v1.w;
            a2 += w.x*v2.x + w.y*v2.y + w.z*v2.z + w.w*v2.w;
        }
        g_u1[idx] = a1; g_u2[idx] = a2;
    }
}

// ---------------- per-node dst-side attention term p[n] = att_b + x[n].w1 -------------
__global__ void k_p(const float* __restrict__ x, const float* __restrict__ att_w,
                    const float* __restrict__ att_b)
{
    int n = blockIdx.x * blockDim.x + threadIdx.x;
    if (n >= MM) return;
    float acc = att_b[0];
    const float4* xr = (const float4*)(x + (long)n * DD);
    const float4* wr = (const float4*)att_w;
    #pragma unroll
    for (int k = 0; k < 16; k++) {
        float4 a = xr[k], w = wr[k];
        acc += a.x*w.x + a.y*w.y + a.z*w.z + a.w*w.w;
    }
    g_p[n] = acc;
}

// ---------------- edge logits -> exp(logit) + global sum (no max pass; logits ~O(1)) --
__global__ void k_logitexp(const float* __restrict__ x, const float* __restrict__ u,
                           const int* __restrict__ src, const int* __restrict__ dst,
                           float* __restrict__ psum)
{
    __shared__ float sm[256];
    int e = blockIdx.x * 256 + threadIdx.x;
    float v = 0.f;
    if (e < EE) {
        float acc = g_p[dst[e]];
        const float4* xr = (const float4*)(x + (long)src[e] * DD);
        const float4* ur = (const float4*)(u + g_rel[e] * DD);
        #pragma unroll
        for (int k = 0; k < 16; k++) {
            float4 a = xr[k], w = ur[k];
            acc += a.x*w.x + a.y*w.y + a.z*w.z + a.w*w.w;
        }
        v = __expf(acc);
        g_logit[e] = v;
    }
    sm[threadIdx.x] = v; __syncthreads();
    for (int s = 128; s > 0; s >>= 1) {
        if (threadIdx.x < s) sm[threadIdx.x] += sm[threadIdx.x + s];
        __syncthreads();
    }
    if (threadIdx.x == 0) atomicAdd(psum, sm[0]);
}

// ---------------- message scatter: aggr[dst] += x[src] * alpha (scalar atomics) -------
__global__ void k_scatter(const float* __restrict__ x, const int* __restrict__ src,
                          const int* __restrict__ dst, const float* __restrict__ psum)
{
    long idx = (long)blockIdx.x * 256 + threadIdx.x;
    if (idx >= (long)EE * DD) return;
    int e = (int)(idx >> 6), d = (int)(idx & 63);
    float a = g_logit[e] / *psum;
    atomicAdd(&g_aggr[(long)dst[e]*DD + d], x[(long)src[e]*DD + d] * a);
}

// ---------------- fused losses: kge (blocks < KB) + nt (rest) ----------------
#define KB 512
__global__ void k_loss(const int* __restrict__ src, const int* __restrict__ dst,
                       const float* __restrict__ rel_emb,
                       const int* __restrict__ labels,
                       const float* __restrict__ w_nt, const float* __restrict__ b_nt)
{
    __shared__ float sm[256];
    if (blockIdx.x < KB) {
        float acc = 0.f;
        for (long idx = (long)blockIdx.x * 256 + threadIdx.x; idx < (long)EE * 16;
             idx += (long)KB * 256) {
            int e = (int)(idx >> 4), q = (int)(idx & 15);
            if (g_mask[e] != 0.f) {
                float4 a = *(const float4*)&g_fx[(long)src[e]*DD + q*4];
                float4 b = *(const float4*)&g_fx[(long)dst[e]*DD + q*4];
                float4 r = *(const float4*)&rel_emb[g_rel[e]*DD + q*4];
                float dx = a.x + r.x - b.x;
                float dy = a.y + r.y - b.y;
                float dz = a.z + r.z - b.z;
                float dw = a.w + r.w - b.w;
                acc += dx*dx + dy*dy + dz*dz + dw*dw;
            }
        }
        sm[threadIdx.x] = acc; __syncthreads();
        for (int s = 128; s > 0; s >>= 1) {
            if (threadIdx.x < s) sm[threadIdx.x] += sm[threadIdx.x + s];
            __syncthreads();
        }
        if (threadIdx.x == 0) atomicAdd(&g_kge, sm[0]);
    } else {
        int n = (blockIdx.x - KB) * 256 + threadIdx.x;
        float loss = 0.f;
        if (n < MM) {
            const float* xr = g_fx + (long)n * DD;
            float z0 = b_nt[0], z1 = b_nt[1], z2 = b_nt[2];
            #pragma unroll 16
            for (int k = 0; k < DD; k++) {
                float v = xr[k];
                z0 += v * w_nt[k*3 + 0];
                z1 += v * w_nt[k*3 + 1];
                z2 += v * w_nt[k*3 + 2];
            }
            float mx  = fmaxf(z0, fmaxf(z1, z2));
            float lse = mx + logf(expf(z0 - mx) + expf(z1 - mx) + expf(z2 - mx));
            int lab = labels[n];
            float zl = (lab == 0) ? z0 : ((lab == 1) ? z1 : z2);
            loss = lse - zl;
        }
        sm[threadIdx.x] = loss; __syncthreads();
        for (int s = 128; s > 0; s >>= 1) {
            if (threadIdx.x < s) sm[threadIdx.x] += sm[threadIdx.x + s];
            __syncthreads();
        }
        if (threadIdx.x == 0) atomicAdd(&g_nt, sm[0]);
    }
}

// ---------------- write loss scalars ----------------
__global__ void k_finalize(float* __restrict__ out, long off)
{
    out[off]     = g_kge / (float)((long)EE * DD);
    out[off + 1] = g_nt / (float)MM;
}

// =====================================================================================
extern "C" void kernel_launch(void* const* d_in, const int* in_sizes, int n_in,
                              void* d_out, int out_size)
{
    const int*   node_ids   = (const int*)  d_in[0];
    const int*   edge_index = (const int*)  d_in[1];
    const float* edge_attr  = (const float*)d_in[2];
    const float* tokemb     = (const float*)d_in[3];
    const int*   labels     = (const int*)  d_in[4];
    const float* kg_emb     = (const float*)d_in[5];
    const float* rel_emb    = (const float*)d_in[6];
    const float* w_e2       = (const float*)d_in[7];
    const float* b_e2       = (const float*)d_in[8];
    const float* att1_w     = (const float*)d_in[9];
    const float* att1_b     = (const float*)d_in[10];
    const float* root1      = (const float*)d_in[11];
    const float* bias1      = (const float*)d_in[12];
    const float* att2_w     = (const float*)d_in[13];
    const float* att2_b     = (const float*)d_in[14];
    const float* root2      = (const float*)d_in[15];
    const float* bias2      = (const float*)d_in[16];
    const float* w_lin1     = (const float*)d_in[17];
    const float* b_lin1     = (const float*)d_in[18];
    const float* w_lin2     = (const float*)d_in[19];
    const float* b_lin2     = (const float*)d_in[20];
    const float* w_nt       = (const float*)d_in[21];
    const float* b_nt       = (const float*)d_in[22];
    float* out = (float*)d_out;

    const int* src = edge_index;        // edge_index[0, :]
    const int* dst = edge_index + EE;   // edge_index[1, :]

    void *px_, *ph_, *pfx_, *paggr_, *pW_, *pu1_, *pu2_, *ps1_, *ps2_;
    cudaGetSymbolAddress(&px_,    g_x);
    cudaGetSymbolAddress(&ph_,    g_h);
    cudaGetSymbolAddress(&pfx_,   g_fx);
    cudaGetSymbolAddress(&paggr_, g_aggr);
    cudaGetSymbolAddress(&pu1_,   g_u1);
    cudaGetSymbolAddress(&pu2_,   g_u2);
    cudaGetSymbolAddress(&pW_,    g_W);
    cudaGetSymbolAddress(&ps1_,   g_sum1);
    cudaGetSymbolAddress(&ps2_,   g_sum2);
    float* px    = (float*)px_;
    float* ph    = (float*)ph_;
    float* pfx   = (float*)pfx_;
    float* paggr = (float*)paggr_;
    float* pu1   = (float*)pu1_;
    float* pu2   = (float*)pu2_;
    float* pW    = (float*)pW_;
    float* ps1   = (float*)ps1_;
    float* ps2   = (float*)ps2_;

    // ---- init scratch ----
    k_init<<<(MM*16 + 255)/256, 256>>>(node_ids, kg_emb);

    // ---- tok = token_embeddings @ w_lin1 + b_lin1 (split-K over z, atomic) ----
    {
        dim3 grid(1, (TT + 127)/128, 8);
        gemm_f2<0,0,1,0><<<grid, 256>>>(tokemb, w_lin1, b_lin1, nullptr, px, TT, DD, TOKN, 96);
    }

    // ---- W[r] = relu(rel_emb @ w_e2 + b_e2) as GEMM [50,64]x[64,4096] ----
    {
        dim3 grid(4096/64, 1, 1);
        gemm_f2<1,0,0,0><<<grid, 256>>>(rel_emb, w_e2, b_e2, nullptr, pW, RR, 4096, DD, DD);
    }
    k_edgeprep<<<EB + (RR*DD + 255)/256, 256>>>(edge_attr, att1_w, att2_w);

    // ---- layer 1: x -> h (relu); gemm re-zeroes aggr for layer 2 ----
    k_p<<<(MM + 255)/256, 256>>>(px, att1_w, att1_b);
    k_logitexp<<<(EE + 255)/256, 256>>>(px, pu1, src, dst, ps1);
    k_scatter<<<(int)(((long)EE*DD + 255)/256), 256>>>(px, src, dst, ps1);
    {
        dim3 grid(1, (MM + 127)/128, 1);
        gemm_f2<1,1,0,1><<<grid, 256>>>(px, root1, bias1, paggr, ph, MM, DD, DD, DD);
    }

    // ---- layer 2: h -> final_x ----
    k_p<<<(MM + 255)/256, 256>>>(ph, att2_w, att2_b);
    k_logitexp<<<(EE + 255)/256, 256>>>(ph, pu2, src, dst, ps2);
    k_scatter<<<(int)(((long)EE*DD + 255)/256), 256>>>(ph, src, dst, ps2);
    {
        dim3 grid(1, (MM + 127)/128, 1);
        gemm_f2<0,1,0,0><<<grid, 256>>>(ph, root2, bias2, paggr, pfx, MM, DD, DD, DD);
    }

    // ---- losses (fused) ----
    k_loss<<<KB + (MM + 255)/256, 256>>>(src, dst, rel_emb, labels, w_nt, b_nt);

    // ---- final outputs: final_x @ w_lin2 + b_lin2 ----
    {
        dim3 grid(TOKN/64, (MM + 127)/128, 1);
        gemm_f2<0,0,0,0><<<grid, 256>>>(pfx, w_lin2, b_lin2, nullptr, out, MM, TOKN, DD, DD);
    }

    // ---- loss scalars at the tail of d_out ----
    k_finalize<<<1, 1>>>(out, (long)out_size - 2);
}

// round 11
// speedup vs baseline: 1.3486x; 1.2517x over previous
#include <cuda_runtime.h>
#include <cuda_bf16.h>
#include <stdint.h>
#include <math.h>
#include <float.h>

#define DD   64
#define TT   4096
#define NN   20000
#define MM   24096     // TT + NN
#define EE   100000
#define RR   50
#define TOKN 768

// ---------------- scratch (device globals; no allocation allowed) ----------------
__device__ __align__(16) float g_x[MM*DD];
__device__ __align__(16) float g_h[MM*DD];
__device__ __align__(16) float g_fx[MM*DD];
__device__ __align__(16) float g_aggr[MM*DD];
__device__ __align__(16) float g_W[RR*DD*DD];
__device__ __align__(16) float g_u1[RR*DD];
__device__ __align__(16) float g_u2[RR*DD];
__device__ __align__(16) __nv_bfloat16 g_bhi[TOKN*DD];   // w_lin2^T split hi  [N=768][K=64]
__device__ __align__(16) __nv_bfloat16 g_blo[TOKN*DD];   // w_lin2^T split lo
__device__ int   g_rel[EE];
__device__ float g_mask[EE];
__device__ float g_p[MM];
__device__ float g_logit[EE];
__device__ float g_sum1, g_sum2;
__device__ float g_kge;
__device__ float g_nt;

// ---------------- helpers ----------------
__device__ __forceinline__ unsigned long long fmaf2(unsigned long long a,
                                                    unsigned long long b,
                                                    unsigned long long c) {
    unsigned long long d;
    asm("fma.rn.f32x2 %0, %1, %2, %3;" : "=l"(d) : "l"(a), "l"(b), "l"(c));
    return d;
}

__device__ __forceinline__ float2 u2f(unsigned long long v) {
    float2 r;
    asm("mov.b64 {%0, %1}, %2;" : "=f"(r.x), "=f"(r.y) : "l"(v));
    return r;
}

__device__ __forceinline__ uint32_t pack_bf2(float a, float b) {
    __nv_bfloat162 t = __floats2bfloat162_rn(a, b);
    return *(uint32_t*)&t;
}

// ================= packed-f32x2 GEMM: C[m,n] = A[m,:K] @ B[:K,n] =================
#define LDA 132
#define LDB 136

template<int RELU, int HASADD, int ATOMIC, int ZEROADD>
__global__ void __launch_bounds__(256, 2)
gemm_f2(const float* __restrict__ A, const float* __restrict__ B,
        const float* __restrict__ bias, float* __restrict__ addsrc,
        float* __restrict__ C, int Mrows, int N, int K, int kPerZ)
{
    __shared__ float shA[32*LDA];
    __shared__ float shB[32*LDB];
    int tid  = threadIdx.x;
    int row0 = blockIdx.y * 128;
    int col0 = blockIdx.x * 64;
    int ctid = tid & 15;
    int rtid = tid >> 4;
    int c0 = ctid * 4;
    int r0 = rtid * 8;

    unsigned long long acc[4][4];
    #pragma unroll
    for (int i = 0; i < 4; i++)
        #pragma unroll
        for (int j = 0; j < 4; j++) acc[i][j] = 0ULL;

    int kb = blockIdx.z * kPerZ;
    for (int kc = kb; kc < kb + kPerZ; kc += 32) {
        #pragma unroll
        for (int i = 0; i < 4; i++) {
            int lin = tid + i * 256;
            int row = lin & 127;
            int kq  = lin >> 7;
            float4 v = make_float4(0.f, 0.f, 0.f, 0.f);
            if (row0 + row < Mrows)
                v = *(const float4*)&A[(long)(row0 + row) * K + kc + kq * 4];
            shA[(kq*4 + 0)*LDA + row] = v.x;
            shA[(kq*4 + 1)*LDA + row] = v.y;
            shA[(kq*4 + 2)*LDA + row] = v.z;
            shA[(kq*4 + 3)*LDA + row] = v.w;
        }
        #pragma unroll
        for (int i = 0; i < 2; i++) {
            int lin = tid + i * 256;
            int c4 = lin & 15;
            int k  = lin >> 4;
            float4 v = *(const float4*)&B[(long)(kc + k) * N + col0 + c4 * 4];
            *(float4*)&shB[k*LDB + c4*8]     = make_float4(v.x, v.x, v.y, v.y);
            *(float4*)&shB[k*LDB + c4*8 + 4] = make_float4(v.z, v.z, v.w, v.w);
        }
        __syncthreads();

        #pragma unroll
        for (int k = 0; k < 32; k++) {
            ulonglong2 a01 = *(const ulonglong2*)&shA[k*LDA + r0];
            ulonglong2 a23 = *(const ulonglong2*)&shA[k*LDA + r0 + 4];
            ulonglong2 b01 = *(const ulonglong2*)&shB[k*LDB + c0*2];
            ulonglong2 b23 = *(const ulonglong2*)&shB[k*LDB + c0*2 + 4];
            acc[0][0] = fmaf2(a01.x, b01.x, acc[0][0]);
            acc[0][1] = fmaf2(a01.x, b01.y, acc[0][1]);
            acc[0][2] = fmaf2(a01.x, b23.x, acc[0][2]);
            acc[0][3] = fmaf2(a01.x, b23.y, acc[0][3]);
            acc[1][0] = fmaf2(a01.y, b01.x, acc[1][0]);
            acc[1][1] = fmaf2(a01.y, b01.y, acc[1][1]);
            acc[1][2] = fmaf2(a01.y, b23.x, acc[1][2]);
            acc[1][3] = fmaf2(a01.y, b23.y, acc[1][3]);
            acc[2][0] = fmaf2(a23.x, b01.x, acc[2][0]);
            acc[2][1] = fmaf2(a23.x, b01.y, acc[2][1]);
            acc[2][2] = fmaf2(a23.x, b23.x, acc[2][2]);
            acc[2][3] = fmaf2(a23.x, b23.y, acc[2][3]);
            acc[3][0] = fmaf2(a23.y, b01.x, acc[3][0]);
            acc[3][1] = fmaf2(a23.y, b01.y, acc[3][1]);
            acc[3][2] = fmaf2(a23.y, b23.x, acc[3][2]);
            acc[3][3] = fmaf2(a23.y, b23.y, acc[3][3]);
        }
        __syncthreads();
    }

    float4 bv = *(const float4*)&bias[col0 + c0];
    bool addbias = !ATOMIC || (blockIdx.z == 0);

    #pragma unroll
    for (int rp = 0; rp < 4; rp++) {
        float2 f0 = u2f(acc[rp][0]);
        float2 f1 = u2f(acc[rp][1]);
        float2 f2 = u2f(acc[rp][2]);
        float2 f3 = u2f(acc[rp][3]);
        float4 vlo = make_float4(f0.x, f1.x, f2.x, f3.x);
        float4 vhi = make_float4(f0.y, f1.y, f2.y, f3.y);
        #pragma unroll
        for (int half = 0; half < 2; half++) {
            int row = row0 + r0 + rp*2 + half;
            if (row >= Mrows) continue;
            float4 v = half ? vhi : vlo;
            if (addbias) { v.x += bv.x; v.y += bv.y; v.z += bv.z; v.w += bv.w; }
            if (HASADD) {
                float4 ad = *(float4*)&addsrc[(long)row * N + col0 + c0];
                v.x += ad.x; v.y += ad.y; v.z += ad.z; v.w += ad.w;
                if (ZEROADD)
                    *(float4*)&addsrc[(long)row * N + col0 + c0] =
                        make_float4(0.f, 0.f, 0.f, 0.f);
            }
            if (RELU) {
                v.x = fmaxf(v.x, 0.f); v.y = fmaxf(v.y, 0.f);
                v.z = fmaxf(v.z, 0.f); v.w = fmaxf(v.w, 0.f);
            }
            if (ATOMIC) {
                float* cp = &C[(long)row * N + col0 + c0];
                atomicAdd(cp + 0, v.x); atomicAdd(cp + 1, v.y);
                atomicAdd(cp + 2, v.z); atomicAdd(cp + 3, v.w);
            } else {
                *(float4*)&C[(long)row * N + col0 + c0] = v;
            }
        }
    }
}

// ======== HMMA split-bf16 GEMM: out[M,768] = fx[M,64] @ w_lin2[64,768] + bias ========
// mma.sync.m16n8k16 (target-portable), fp32 accum; hi*hi + hi*lo + lo*hi.
__global__ void k_wsplit(const float* __restrict__ w_lin2)
{
    int idx = blockIdx.x * blockDim.x + threadIdx.x;
    if (idx >= TOKN * DD) return;
    int n = idx >> 6, k = idx & 63;
    float v = w_lin2[(long)k * TOKN + n];
    __nv_bfloat16 hi = __float2bfloat16(v);
    g_bhi[idx] = hi;
    g_blo[idx] = __float2bfloat16(v - __bfloat162float(hi));
}

__device__ __forceinline__ void mma_bf16(float* c, const uint32_t* a,
                                         uint32_t b0, uint32_t b1) {
    asm volatile(
        "mma.sync.aligned.m16n8k16.row.col.f32.bf16.bf16.f32 "
        "{%0,%1,%2,%3}, {%4,%5,%6,%7}, {%8,%9}, {%0,%1,%2,%3};"
        : "+f"(c[0]), "+f"(c[1]), "+f"(c[2]), "+f"(c[3])
        : "r"(a[0]), "r"(a[1]), "r"(a[2]), "r"(a[3]), "r"(b0), "r"(b1));
}

#define BSTR 72   // smem B row stride in bf16 (conflict-free frag loads)

__global__ void __launch_bounds__(256, 2)
k_gemm_mma(const float* __restrict__ A, const float* __restrict__ bias,
           float* __restrict__ out)
{
    __shared__ __nv_bfloat16 smBhi[64 * BSTR];
    __shared__ __nv_bfloat16 smBlo[64 * BSTR];
    int tid  = threadIdx.x;
    int wid  = tid >> 5;
    int lane = tid & 31;
    int g    = lane >> 2;     // 0..7
    int tg   = lane & 3;      // 0..3
    int col0 = blockIdx.x * 64;
    int row0 = blockIdx.y * 128;

    // stage B tile [64 n][64 k] bf16 (hi/lo) into padded smem
    for (int i = tid; i < 64 * 16; i += 256) {
        int n = i >> 4, q = i & 15;                  // q: 4-bf16 chunk
        uint2 h = *(const uint2*)&g_bhi[(long)(col0 + n) * DD + q * 4];
        uint2 l = *(const uint2*)&g_blo[(long)(col0 + n) * DD + q * 4];
        *(uint2*)&smBhi[n * BSTR + q * 4] = h;
        *(uint2*)&smBlo[n * BSTR + q * 4] = l;
    }
    __syncthreads();

    float acc[8][4];
    #pragma unroll
    for (int nt = 0; nt < 8; nt++)
        #pragma unroll
        for (int j = 0; j < 4; j++) acc[nt][j] = 0.f;

    int rbase = row0 + wid * 16;

    #pragma unroll
    for (int ks = 0; ks < 4; ks++) {
        int k0 = ks * 16;
        // A fragments from global fp32 (L2-resident), split hi/lo in regs
        uint32_t ahi[4], alo[4];
        #pragma unroll
        for (int i = 0; i < 4; i++) {
            int r = rbase + g + (i & 1) * 8;
            int k = k0 + tg * 2 + (i >> 1) * 8;
            float2 v = make_float2(0.f, 0.f);
            if (r < MM) v = *(const float2*)&A[(long)r * DD + k];
            float hx = __bfloat162float(__float2bfloat16(v.x));
            float hy = __bfloat162float(__float2bfloat16(v.y));
            ahi[i] = pack_bf2(v.x, v.y);
            alo[i] = pack_bf2(v.x - hx, v.y - hy);
        }
        #pragma unroll
        for (int nt = 0; nt < 8; nt++) {
            int n = nt * 8 + g;
            uint32_t b0h = *(const uint32_t*)&smBhi[n * BSTR + k0 + tg * 2];
            uint32_t b1h = *(const uint32_t*)&smBhi[n * BSTR + k0 + tg * 2 + 8];
            uint32_t b0l = *(const uint32_t*)&smBlo[n * BSTR + k0 + tg * 2];
            uint32_t b1l = *(const uint32_t*)&smBlo[n * BSTR + k0 + tg * 2 + 8];
            mma_bf16(acc[nt], ahi, b0h, b1h);
            mma_bf16(acc[nt], ahi, b0l, b1l);
            mma_bf16(acc[nt], alo, b0h, b1h);
        }
    }

    // epilogue: + bias, float2 stores
    #pragma unroll
    for (int nt = 0; nt < 8; nt++) {
        int c = col0 + nt * 8 + tg * 2;
        float2 bv = *(const float2*)&bias[c];
        int r0w = rbase + g;
        if (r0w < MM)
            *(float2*)&out[(long)r0w * TOKN + c] =
                make_float2(acc[nt][0] + bv.x, acc[nt][1] + bv.y);
        int r1w = rbase + g + 8;
        if (r1w < MM)
            *(float2*)&out[(long)r1w * TOKN + c] =
                make_float2(acc[nt][2] + bv.x, acc[nt][3] + bv.y);
    }
}

// ---------------- init: zero aggr + tok region of x, gather kg nodes, reset scalars ----
__global__ void k_init(const int* __restrict__ node_ids, const float* __restrict__ kg_emb)
{
    int idx = blockIdx.x * blockDim.x + threadIdx.x;   // float4 units
    float4 z = make_float4(0.f, 0.f, 0.f, 0.f);
    if (idx < MM*16) ((float4*)g_aggr)[idx] = z;
    if (idx < TT*16) ((float4*)g_x)[idx] = z;
    if (idx < NN*16) {
        int n = idx >> 4, q = idx & 15;
        ((float4*)g_x)[(long)(TT + n)*16 + q] =
            ((const float4*)kg_emb)[(long)node_ids[n]*16 + q];
    }
    if (idx == 0) { g_kge = 0.f; g_nt = 0.f; g_sum1 = 0.f; g_sum2 = 0.f; }
}

// ---------------- edge prep: relation id + mask (float4 smem staging); u tables -------
#define EPB 128
#define EB  ((EE + EPB - 1) / EPB)
__global__ void k_edgeprep(const float* __restrict__ ea,
                           const float* __restrict__ att1_w,
                           const float* __restrict__ att2_w)
{
    int b = blockIdx.x;
    if (b < EB) {
        __shared__ float smr[EPB * RR];
        int e0 = b * EPB;
        int cnt = min(EPB, EE - e0);
        int total4 = (cnt * RR) >> 2;
        const float4* base4 = (const float4*)(ea + (long)e0 * RR);
        float4* sm4 = (float4*)smr;
        for (int i = threadIdx.x; i < total4; i += 256) sm4[i] = base4[i];
        __syncthreads();
        int el = threadIdx.x;
        if (el < cnt) {
            const float* row = smr + el * RR;
            float acc = 0.f;
            #pragma unroll
            for (int r = 1; r < RR; r++) acc += row[r] * (float)r;
            g_rel[e0 + el] = (int)(acc + 0.5f);
            g_mask[e0 + el] = (row[47] + row[48] + row[49] == 0.f) ? 1.f : 0.f;
        }
    } else {
        int idx = (b - EB) * 256 + threadIdx.x;
        if (idx >= RR*DD) return;
        int rel = idx >> 6, d = idx & 63;
        const float4* wrow = (const float4*)(g_W + (long)rel*4096 + d*64);
        const float4* w1 = (const float4*)(att1_w + 64);
        const float4* w2 = (const float4*)(att2_w + 64);
        float a1 = 0.f, a2 = 0.f;
        #pragma unroll
        for (int o = 0; o < 16; o++) {
            float4 w = wrow[o];
            float4 v1 = w1[o], v2 = w2[o];
            a1 += w.x*v1.x + w.y*v1.y + w.z*v1.z + w.w*v1.w;
            a2 += w.x*v2.x + w.y*v2.y + w.z*v2.z + w.w*v2.w;
        }
        g_u1[idx] = a1; g_u2[idx] = a2;
    }
}

// ---------------- per-node dst-side attention term p[n] = att_b + x[n].w1 -------------
__global__ void k_p(const float* __restrict__ x, const float* __restrict__ att_w,
                    const float* __restrict__ att_b)
{
    int n = blockIdx.x * blockDim.x + threadIdx.x;
    if (n >= MM) return;
    float acc = att_b[0];
    const float4* xr = (const float4*)(x + (long)n * DD);
    const float4* wr = (const float4*)att_w;
    #pragma unroll
    for (int k = 0; k < 16; k++) {
        float4 a = xr[k], w = wr[k];
        acc += a.x*w.x + a.y*w.y + a.z*w.z + a.w*w.w;
    }
    g_p[n] = acc;
}

// ---------------- edge logits -> exp(logit) + global sum (no max pass; logits ~O(1)) --
__global__ void k_logitexp(const float* __restrict__ x, const float* __restrict__ u,
                           const int* __restrict__ src, const int* __restrict__ dst,
                           float* __restrict__ psum)
{
    __shared__ float smr[256];
    int e = blockIdx.x * 256 + threadIdx.x;
    float v = 0.f;
    if (e < EE) {
        float acc = g_p[dst[e]];
        const float4* xr = (const float4*)(x + (long)src[e] * DD);
        const float4* ur = (const float4*)(u + g_rel[e] * DD);
        #pragma unroll
        for (int k = 0; k < 16; k++) {
            float4 a = xr[k], w = ur[k];
            acc += a.x*w.x + a.y*w.y + a.z*w.z + a.w*w.w;
        }
        v = __expf(acc);
        g_logit[e] = v;
    }
    smr[threadIdx.x] = v; __syncthreads();
    for (int s = 128; s > 0; s >>= 1) {
        if (threadIdx.x < s) smr[threadIdx.x] += smr[threadIdx.x + s];
        __syncthreads();
    }
    if (threadIdx.x == 0) atomicAdd(psum, smr[0]);
}

// ---------------- message scatter: aggr[dst] += x[src] * alpha (scalar atomics) -------
__global__ void k_scatter(const float* __restrict__ x, const int* __restrict__ src,
                          const int* __restrict__ dst, const float* __restrict__ psum)
{
    long idx = (long)blockIdx.x * 256 + threadIdx.x;
    if (idx >= (long)EE * DD) return;
    int e = (int)(idx >> 6), d = (int)(idx & 63);
    float a = g_logit[e] / *psum;
    atomicAdd(&g_aggr[(long)dst[e]*DD + d], x[(long)src[e]*DD + d] * a);
}

// ---------------- fused losses: kge (blocks < KB) + nt (rest) ----------------
#define KB 512
__global__ void k_loss(const int* __restrict__ src, const int* __restrict__ dst,
                       const float* __restrict__ rel_emb,
                       const int* __restrict__ labels,
                       const float* __restrict__ w_nt, const float* __restrict__ b_nt)
{
    __shared__ float smr[256];
    if (blockIdx.x < KB) {
        float acc = 0.f;
        for (long idx = (long)blockIdx.x * 256 + threadIdx.x; idx < (long)EE * 16;
             idx += (long)KB * 256) {
            int e = (int)(idx >> 4), q = (int)(idx & 15);
            if (g_mask[e] != 0.f) {
                float4 a = *(const float4*)&g_fx[(long)src[e]*DD + q*4];
                float4 b = *(const float4*)&g_fx[(long)dst[e]*DD + q*4];
                float4 r = *(const float4*)&rel_emb[g_rel[e]*DD + q*4];
                float dx = a.x + r.x - b.x;
                float dy = a.y + r.y - b.y;
                float dz = a.z + r.z - b.z;
                float dw = a.w + r.w - b.w;
                acc += dx*dx + dy*dy + dz*dz + dw*dw;
            }
        }
        smr[threadIdx.x] = acc; __syncthreads();
        for (int s = 128; s > 0; s >>= 1) {
            if (threadIdx.x < s) smr[threadIdx.x] += smr[threadIdx.x + s];
            __syncthreads();
        }
        if (threadIdx.x == 0) atomicAdd(&g_kge, smr[0]);
    } else {
        int n = (blockIdx.x - KB) * 256 + threadIdx.x;
        float loss = 0.f;
        if (n < MM) {
            const float* xr = g_fx + (long)n * DD;
            float z0 = b_nt[0], z1 = b_nt[1], z2 = b_nt[2];
            #pragma unroll 16
            for (int k = 0; k < DD; k++) {
                float v = xr[k];
                z0 += v * w_nt[k*3 + 0];
                z1 += v * w_nt[k*3 + 1];
                z2 += v * w_nt[k*3 + 2];
            }
            float mx  = fmaxf(z0, fmaxf(z1, z2));
            float lse = mx + logf(expf(z0 - mx) + expf(z1 - mx) + expf(z2 - mx));
            int lab = labels[n];
            float zl = (lab == 0) ? z0 : ((lab == 1) ? z1 : z2);
            loss = lse - zl;
        }
        smr[threadIdx.x] = loss; __syncthreads();
        for (int s = 128; s > 0; s >>= 1) {
            if (threadIdx.x < s) smr[threadIdx.x] += smr[threadIdx.x + s];
            __syncthreads();
        }
        if (threadIdx.x == 0) atomicAdd(&g_nt, smr[0]);
    }
}

// ---------------- write loss scalars ----------------
__global__ void k_finalize(float* __restrict__ out, long off)
{
    out[off]     = g_kge / (float)((long)EE * DD);
    out[off + 1] = g_nt / (float)MM;
}

// =====================================================================================
extern "C" void kernel_launch(void* const* d_in, const int* in_sizes, int n_in,
                              void* d_out, int out_size)
{
    const int*   node_ids   = (const int*)  d_in[0];
    const int*   edge_index = (const int*)  d_in[1];
    const float* edge_attr  = (const float*)d_in[2];
    const float* tokemb     = (const float*)d_in[3];
    const int*   labels     = (const int*)  d_in[4];
    const float* kg_emb     = (const float*)d_in[5];
    const float* rel_emb    = (const float*)d_in[6];
    const float* w_e2       = (const float*)d_in[7];
    const float* b_e2       = (const float*)d_in[8];
    const float* att1_w     = (const float*)d_in[9];
    const float* att1_b     = (const float*)d_in[10];
    const float* root1      = (const float*)d_in[11];
    const float* bias1      = (const float*)d_in[12];
    const float* att2_w     = (const float*)d_in[13];
    const float* att2_b     = (const float*)d_in[14];
    const float* root2      = (const float*)d_in[15];
    const float* bias2      = (const float*)d_in[16];
    const float* w_lin1     = (const float*)d_in[17];
    const float* b_lin1     = (const float*)d_in[18];
    const float* w_lin2     = (const float*)d_in[19];
    const float* b_lin2     = (const float*)d_in[20];
    const float* w_nt       = (const float*)d_in[21];
    const float* b_nt       = (const float*)d_in[22];
    float* out = (float*)d_out;

    const int* src = edge_index;        // edge_index[0, :]
    const int* dst = edge_index + EE;   // edge_index[1, :]

    void *px_, *ph_, *pfx_, *paggr_, *pW_, *pu1_, *pu2_, *ps1_, *ps2_;
    cudaGetSymbolAddress(&px_,    g_x);
    cudaGetSymbolAddress(&ph_,    g_h);
    cudaGetSymbolAddress(&pfx_,   g_fx);
    cudaGetSymbolAddress(&paggr_, g_aggr);
    cudaGetSymbolAddress(&pu1_,   g_u1);
    cudaGetSymbolAddress(&pu2_,   g_u2);
    cudaGetSymbolAddress(&pW_,    g_W);
    cudaGetSymbolAddress(&ps1_,   g_sum1);
    cudaGetSymbolAddress(&ps2_,   g_sum2);
    float* px    = (float*)px_;
    float* ph    = (float*)ph_;
    float* pfx   = (float*)pfx_;
    float* paggr = (float*)paggr_;
    float* pu1   = (float*)pu1_;
    float* pu2   = (float*)pu2_;
    float* pW    = (float*)pW_;
    float* ps1   = (float*)ps1_;
    float* ps2   = (float*)ps2_;

    // ---- init scratch + weight split ----
    k_init<<<(MM*16 + 255)/256, 256>>>(node_ids, kg_emb);
    k_wsplit<<<(TOKN*DD + 255)/256, 256>>>(w_lin2);

    // ---- tok = token_embeddings @ w_lin1 + b_lin1 (split-K over z, atomic) ----
    {
        dim3 grid(1, (TT + 127)/128, 8);
        gemm_f2<0,0,1,0><<<grid, 256>>>(tokemb, w_lin1, b_lin1, nullptr, px, TT, DD, TOKN, 96);
    }

    // ---- W[r] = relu(rel_emb @ w_e2 + b_e2) as GEMM [50,64]x[64,4096] ----
    {
        dim3 grid(4096/64, 1, 1);
        gemm_f2<1,0,0,0><<<grid, 256>>>(rel_emb, w_e2, b_e2, nullptr, pW, RR, 4096, DD, DD);
    }
    k_edgeprep<<<EB + (RR*DD + 255)/256, 256>>>(edge_attr, att1_w, att2_w);

    // ---- layer 1: x -> h (relu); gemm re-zeroes aggr for layer 2 ----
    k_p<<<(MM + 255)/256, 256>>>(px, att1_w, att1_b);
    k_logitexp<<<(EE + 255)/256, 256>>>(px, pu1, src, dst, ps1);
    k_scatter<<<(int)(((long)EE*DD + 255)/256), 256>>>(px, src, dst, ps1);
    {
        dim3 grid(1, (MM + 127)/128, 1);
        gemm_f2<1,1,0,1><<<grid, 256>>>(px, root1, bias1, paggr, ph, MM, DD, DD, DD);
    }

    // ---- layer 2: h -> final_x ----
    k_p<<<(MM + 255)/256, 256>>>(ph, att2_w, att2_b);
    k_logitexp<<<(EE + 255)/256, 256>>>(ph, pu2, src, dst, ps2);
    k_scatter<<<(int)(((long)EE*DD + 255)/256), 256>>>(ph, src, dst, ps2);
    {
        dim3 grid(1, (MM + 127)/128, 1);
        gemm_f2<0,1,0,0><<<grid, 256>>>(ph, root2, bias2, paggr, pfx, MM, DD, DD, DD);
    }

    // ---- losses (fused) ----
    k_loss<<<KB + (MM + 255)/256, 256>>>(src, dst, rel_emb, labels, w_nt, b_nt);

    // ---- final outputs via HMMA split-bf16: final_x @ w_lin2 + b_lin2 ----
    {
        dim3 grid(TOKN/64, (MM + 127)/128, 1);
        k_gemm_mma<<<grid, 256>>>(pfx, b_lin2, out);
    }

    // ---- loss scalars at the tail of d_out ----
    k_finalize<<<1, 1>>>(out, (long)out_size - 2);
}

// round 12
// speedup vs baseline: 1.3494x; 1.0006x over previous
#include <cuda_runtime.h>
#include <cuda_bf16.h>
#include <stdint.h>
#include <math.h>
#include <float.h>

#define DD   64
#define TT   4096
#define NN   20000
#define MM   24096     // TT + NN
#define EE   100000
#define RR   50
#define TOKN 768

// ---------------- scratch (device globals; no allocation allowed) ----------------
__device__ __align__(16) float g_x[MM*DD];
__device__ __align__(16) float g_h[MM*DD];
__device__ __align__(16) float g_fx[MM*DD];
__device__ __align__(16) float g_aggr[MM*DD];
__device__ __align__(16) float g_u1[RR*DD];
__device__ __align__(16) float g_u2[RR*DD];
__device__ __align__(16) __nv_bfloat16 g_bhi[TOKN*DD];   // w_lin2^T split hi  [N=768][K=64]
__device__ __align__(16) __nv_bfloat16 g_blo[TOKN*DD];   // w_lin2^T split lo
__device__ int   g_rel[EE];
__device__ float g_mask[EE];
__device__ float g_p[MM];
__device__ float g_logit[EE];
__device__ float g_sum1, g_sum2;
__device__ float g_kge;
__device__ float g_nt;

// ---------------- helpers ----------------
__device__ __forceinline__ unsigned long long fmaf2(unsigned long long a,
                                                    unsigned long long b,
                                                    unsigned long long c) {
    unsigned long long d;
    asm("fma.rn.f32x2 %0, %1, %2, %3;" : "=l"(d) : "l"(a), "l"(b), "l"(c));
    return d;
}

__device__ __forceinline__ float2 u2f(unsigned long long v) {
    float2 r;
    asm("mov.b64 {%0, %1}, %2;" : "=f"(r.x), "=f"(r.y) : "l"(v));
    return r;
}

__device__ __forceinline__ uint32_t pack_bf2(float a, float b) {
    __nv_bfloat162 t = __floats2bfloat162_rn(a, b);
    return *(uint32_t*)&t;
}

// ================= packed-f32x2 GEMM: C[m,n] = A[m,:K] @ B[:K,n] =================
#define LDA 132
#define LDB 136

template<int RELU, int HASADD, int ATOMIC, int ZEROADD>
__global__ void __launch_bounds__(256, 2)
gemm_f2(const float* __restrict__ A, const float* __restrict__ B,
        const float* __restrict__ bias, float* __restrict__ addsrc,
        float* __restrict__ C, int Mrows, int N, int K, int kPerZ)
{
    __shared__ float shA[32*LDA];
    __shared__ float shB[32*LDB];
    int tid  = threadIdx.x;
    int row0 = blockIdx.y * 128;
    int col0 = blockIdx.x * 64;
    int ctid = tid & 15;
    int rtid = tid >> 4;
    int c0 = ctid * 4;
    int r0 = rtid * 8;

    unsigned long long acc[4][4];
    #pragma unroll
    for (int i = 0; i < 4; i++)
        #pragma unroll
        for (int j = 0; j < 4; j++) acc[i][j] = 0ULL;

    int kb = blockIdx.z * kPerZ;
    for (int kc = kb; kc < kb + kPerZ; kc += 32) {
        #pragma unroll
        for (int i = 0; i < 4; i++) {
            int lin = tid + i * 256;
            int row = lin & 127;
            int kq  = lin >> 7;
            float4 v = make_float4(0.f, 0.f, 0.f, 0.f);
            if (row0 + row < Mrows)
                v = *(const float4*)&A[(long)(row0 + row) * K + kc + kq * 4];
            shA[(kq*4 + 0)*LDA + row] = v.x;
            shA[(kq*4 + 1)*LDA + row] = v.y;
            shA[(kq*4 + 2)*LDA + row] = v.z;
            shA[(kq*4 + 3)*LDA + row] = v.w;
        }
        #pragma unroll
        for (int i = 0; i < 2; i++) {
            int lin = tid + i * 256;
            int c4 = lin & 15;
            int k  = lin >> 4;
            float4 v = *(const float4*)&B[(long)(kc + k) * N + col0 + c4 * 4];
            *(float4*)&shB[k*LDB + c4*8]     = make_float4(v.x, v.x, v.y, v.y);
            *(float4*)&shB[k*LDB + c4*8 + 4] = make_float4(v.z, v.z, v.w, v.w);
        }
        __syncthreads();

        #pragma unroll
        for (int k = 0; k < 32; k++) {
            ulonglong2 a01 = *(const ulonglong2*)&shA[k*LDA + r0];
            ulonglong2 a23 = *(const ulonglong2*)&shA[k*LDA + r0 + 4];
            ulonglong2 b01 = *(const ulonglong2*)&shB[k*LDB + c0*2];
            ulonglong2 b23 = *(const ulonglong2*)&shB[k*LDB + c0*2 + 4];
            acc[0][0] = fmaf2(a01.x, b01.x, acc[0][0]);
            acc[0][1] = fmaf2(a01.x, b01.y, acc[0][1]);
            acc[0][2] = fmaf2(a01.x, b23.x, acc[0][2]);
            acc[0][3] = fmaf2(a01.x, b23.y, acc[0][3]);
            acc[1][0] = fmaf2(a01.y, b01.x, acc[1][0]);
            acc[1][1] = fmaf2(a01.y, b01.y, acc[1][1]);
            acc[1][2] = fmaf2(a01.y, b23.x, acc[1][2]);
            acc[1][3] = fmaf2(a01.y, b23.y, acc[1][3]);
            acc[2][0] = fmaf2(a23.x, b01.x, acc[2][0]);
            acc[2][1] = fmaf2(a23.x, b01.y, acc[2][1]);
            acc[2][2] = fmaf2(a23.x, b23.x, acc[2][2]);
            acc[2][3] = fmaf2(a23.x, b23.y, acc[2][3]);
            acc[3][0] = fmaf2(a23.y, b01.x, acc[3][0]);
            acc[3][1] = fmaf2(a23.y, b01.y, acc[3][1]);
            acc[3][2] = fmaf2(a23.y, b23.x, acc[3][2]);
            acc[3][3] = fmaf2(a23.y, b23.y, acc[3][3]);
        }
        __syncthreads();
    }

    float4 bv = *(const float4*)&bias[col0 + c0];
    bool addbias = !ATOMIC || (blockIdx.z == 0);

    #pragma unroll
    for (int rp = 0; rp < 4; rp++) {
        float2 f0 = u2f(acc[rp][0]);
        float2 f1 = u2f(acc[rp][1]);
        float2 f2 = u2f(acc[rp][2]);
        float2 f3 = u2f(acc[rp][3]);
        float4 vlo = make_float4(f0.x, f1.x, f2.x, f3.x);
        float4 vhi = make_float4(f0.y, f1.y, f2.y, f3.y);
        #pragma unroll
        for (int half = 0; half < 2; half++) {
            int row = row0 + r0 + rp*2 + half;
            if (row >= Mrows) continue;
            float4 v = half ? vhi : vlo;
            if (addbias) { v.x += bv.x; v.y += bv.y; v.z += bv.z; v.w += bv.w; }
            if (HASADD) {
                float4 ad = *(float4*)&addsrc[(long)row * N + col0 + c0];
                v.x += ad.x; v.y += ad.y; v.z += ad.z; v.w += ad.w;
                if (ZEROADD)
                    *(float4*)&addsrc[(long)row * N + col0 + c0] =
                        make_float4(0.f, 0.f, 0.f, 0.f);
            }
            if (RELU) {
                v.x = fmaxf(v.x, 0.f); v.y = fmaxf(v.y, 0.f);
                v.z = fmaxf(v.z, 0.f); v.w = fmaxf(v.w, 0.f);
            }
            if (ATOMIC) {
                float* cp = &C[(long)row * N + col0 + c0];
                atomicAdd(cp + 0, v.x); atomicAdd(cp + 1, v.y);
                atomicAdd(cp + 2, v.z); atomicAdd(cp + 3, v.w);
            } else {
                *(float4*)&C[(long)row * N + col0 + c0] = v;
            }
        }
    }
}

// ======== HMMA split-bf16 GEMM: out[M,768] = fx[M,64] @ w_lin2[64,768] + bias ========
__global__ void k_wsplit(const float* __restrict__ w_lin2)
{
    int idx = blockIdx.x * blockDim.x + threadIdx.x;
    if (idx >= TOKN * DD) return;
    int n = idx >> 6, k = idx & 63;
    float v = w_lin2[(long)k * TOKN + n];
    __nv_bfloat16 hi = __float2bfloat16(v);
    g_bhi[idx] = hi;
    g_blo[idx] = __float2bfloat16(v - __bfloat162float(hi));
}

__device__ __forceinline__ void mma_bf16(float* c, const uint32_t* a,
                                         uint32_t b0, uint32_t b1) {
    asm volatile(
        "mma.sync.aligned.m16n8k16.row.col.f32.bf16.bf16.f32 "
        "{%0,%1,%2,%3}, {%4,%5,%6,%7}, {%8,%9}, {%0,%1,%2,%3};"
        : "+f"(c[0]), "+f"(c[1]), "+f"(c[2]), "+f"(c[3])
        : "r"(a[0]), "r"(a[1]), "r"(a[2]), "r"(a[3]), "r"(b0), "r"(b1));
}

#define BSTR 72   // smem B row stride in bf16

__global__ void __launch_bounds__(256, 2)
k_gemm_mma(const float* __restrict__ A, const float* __restrict__ bias,
           float* __restrict__ out)
{
    __shared__ __nv_bfloat16 smBhi[64 * BSTR];
    __shared__ __nv_bfloat16 smBlo[64 * BSTR];
    int tid  = threadIdx.x;
    int wid  = tid >> 5;
    int lane = tid & 31;
    int g    = lane >> 2;
    int tg   = lane & 3;
    int col0 = blockIdx.x * 64;
    int row0 = blockIdx.y * 128;

    for (int i = tid; i < 64 * 16; i += 256) {
        int n = i >> 4, q = i & 15;
        uint2 h = *(const uint2*)&g_bhi[(long)(col0 + n) * DD + q * 4];
        uint2 l = *(const uint2*)&g_blo[(long)(col0 + n) * DD + q * 4];
        *(uint2*)&smBhi[n * BSTR + q * 4] = h;
        *(uint2*)&smBlo[n * BSTR + q * 4] = l;
    }
    __syncthreads();

    float acc[8][4];
    #pragma unroll
    for (int nt = 0; nt < 8; nt++)
        #pragma unroll
        for (int j = 0; j < 4; j++) acc[nt][j] = 0.f;

    int rbase = row0 + wid * 16;

    #pragma unroll
    for (int ks = 0; ks < 4; ks++) {
        int k0 = ks * 16;
        uint32_t ahi[4], alo[4];
        #pragma unroll
        for (int i = 0; i < 4; i++) {
            int r = rbase + g + (i & 1) * 8;
            int k = k0 + tg * 2 + (i >> 1) * 8;
            float2 v = make_float2(0.f, 0.f);
            if (r < MM) v = *(const float2*)&A[(long)r * DD + k];
            float hx = __bfloat162float(__float2bfloat16(v.x));
            float hy = __bfloat162float(__float2bfloat16(v.y));
            ahi[i] = pack_bf2(v.x, v.y);
            alo[i] = pack_bf2(v.x - hx, v.y - hy);
        }
        #pragma unroll
        for (int nt = 0; nt < 8; nt++) {
            int n = nt * 8 + g;
            uint32_t b0h = *(const uint32_t*)&smBhi[n * BSTR + k0 + tg * 2];
            uint32_t b1h = *(const uint32_t*)&smBhi[n * BSTR + k0 + tg * 2 + 8];
            uint32_t b0l = *(const uint32_t*)&smBlo[n * BSTR + k0 + tg * 2];
            uint32_t b1l = *(const uint32_t*)&smBlo[n * BSTR + k0 + tg * 2 + 8];
            mma_bf16(acc[nt], ahi, b0h, b1h);
            mma_bf16(acc[nt], ahi, b0l, b1l);
            mma_bf16(acc[nt], alo, b0h, b1h);
        }
    }

    #pragma unroll
    for (int nt = 0; nt < 8; nt++) {
        int c = col0 + nt * 8 + tg * 2;
        float2 bv = *(const float2*)&bias[c];
        int r0w = rbase + g;
        if (r0w < MM)
            *(float2*)&out[(long)r0w * TOKN + c] =
                make_float2(acc[nt][0] + bv.x, acc[nt][1] + bv.y);
        int r1w = rbase + g + 8;
        if (r1w < MM)
            *(float2*)&out[(long)r1w * TOKN + c] =
                make_float2(acc[nt][2] + bv.x, acc[nt][3] + bv.y);
    }
}

// ---------------- init: zero aggr, gather kg nodes, reset scalars ----------------
__global__ void k_init(const int* __restrict__ node_ids, const float* __restrict__ kg_emb)
{
    int idx = blockIdx.x * blockDim.x + threadIdx.x;   // float4 units
    float4 z = make_float4(0.f, 0.f, 0.f, 0.f);
    if (idx < MM*16) ((float4*)g_aggr)[idx] = z;
    if (idx < NN*16) {
        int n = idx >> 4, q = idx & 15;
        ((float4*)g_x)[(long)(TT + n)*16 + q] =
            ((const float4*)kg_emb)[(long)node_ids[n]*16 + q];
    }
    if (idx == 0) { g_kge = 0.f; g_nt = 0.f; g_sum1 = 0.f; g_sum2 = 0.f; }
}

// ---------------- zero token region of x (separate stream, before token gemm) ---------
__global__ void k_zerotok()
{
    int idx = blockIdx.x * blockDim.x + threadIdx.x;
    if (idx < TT*16) ((float4*)g_x)[idx] = make_float4(0.f, 0.f, 0.f, 0.f);
}

// ---------------- relation id + mask (float4 smem staging) ----------------
#define EPB 128
#define EB  ((EE + EPB - 1) / EPB)
__global__ void k_relmask(const float* __restrict__ ea)
{
    __shared__ float smr[EPB * RR];
    int e0 = blockIdx.x * EPB;
    int cnt = min(EPB, EE - e0);
    int total4 = (cnt * RR) >> 2;
    const float4* base4 = (const float4*)(ea + (long)e0 * RR);
    float4* sm4 = (float4*)smr;
    for (int i = threadIdx.x; i < total4; i += 256) sm4[i] = base4[i];
    __syncthreads();
    int el = threadIdx.x;
    if (el < cnt) {
        const float* row = smr + el * RR;
        float acc = 0.f;
        #pragma unroll
        for (int r = 1; r < RR; r++) acc += row[r] * (float)r;
        g_rel[e0 + el] = (int)(acc + 0.5f);
        g_mask[e0 + el] = (row[47] + row[48] + row[49] == 0.f) ? 1.f : 0.f;
    }
}

// ---- fused u-tables: u{1,2}[rel][d] = sum_o relu(rel_emb[rel].w_e2[:,d*64+o]+b)*attw[64+o]
__global__ void __launch_bounds__(256)
k_ufused(const float* __restrict__ rel_emb, const float* __restrict__ w_e2,
         const float* __restrict__ b_e2,
         const float* __restrict__ att1_w, const float* __restrict__ att2_w)
{
    __shared__ float ws[64*64];     // w_e2 column block for this d
    __shared__ float re[RR*64];     // all relation embeddings
    int tid = threadIdx.x;
    int d = blockIdx.x;

    for (int i = tid; i < 64*64; i += 256) {
        int k = i >> 6, o = i & 63;
        ws[i] = w_e2[(long)k*4096 + d*64 + o];
    }
    for (int i = tid; i < RR*64; i += 256) re[i] = rel_emb[i];
    __syncthreads();

    int wid = tid >> 5, lane = tid & 31;
    float b1 = b_e2[d*64 + lane];
    float b2 = b_e2[d*64 + lane + 32];
    float w1a = att1_w[64 + lane], w1b = att1_w[64 + lane + 32];
    float w2a = att2_w[64 + lane], w2b = att2_w[64 + lane + 32];

    for (int rel = wid; rel < RR; rel += 8) {
        float acc1 = b1, acc2 = b2;
        const float* rr = re + rel*64;
        #pragma unroll
        for (int k = 0; k < 64; k++) {
            float rv = rr[k];
            acc1 += rv * ws[k*64 + lane];
            acc2 += rv * ws[k*64 + lane + 32];
        }
        acc1 = fmaxf(acc1, 0.f); acc2 = fmaxf(acc2, 0.f);
        float a1 = acc1*w1a + acc2*w1b;
        float a2 = acc1*w2a + acc2*w2b;
        #pragma unroll
        for (int s = 16; s; s >>= 1) {
            a1 += __shfl_down_sync(0xffffffff, a1, s);
            a2 += __shfl_down_sync(0xffffffff, a2, s);
        }
        if (lane == 0) { g_u1[rel*64 + d] = a1; g_u2[rel*64 + d] = a2; }
    }
}

// ---------------- per-node dst-side attention term p[n] = att_b + x[n].w1 -------------
__global__ void k_p(const float* __restrict__ x, const float* __restrict__ att_w,
                    const float* __restrict__ att_b)
{
    int n = blockIdx.x * blockDim.x + threadIdx.x;
    if (n >= MM) return;
    float acc = att_b[0];
    const float4* xr = (const float4*)(x + (long)n * DD);
    const float4* wr = (const float4*)att_w;
    #pragma unroll
    for (int k = 0; k < 16; k++) {
        float4 a = xr[k], w = wr[k];
        acc += a.x*w.x + a.y*w.y + a.z*w.z + a.w*w.w;
    }
    g_p[n] = acc;
}

// ---------------- edge logits -> exp(logit) + global sum ----------------
__global__ void k_logitexp(const float* __restrict__ x, const float* __restrict__ u,
                           const int* __restrict__ src, const int* __restrict__ dst,
                           float* __restrict__ psum)
{
    __shared__ float smr[256];
    int e = blockIdx.x * 256 + threadIdx.x;
    float v = 0.f;
    if (e < EE) {
        float acc = g_p[dst[e]];
        const float4* xr = (const float4*)(x + (long)src[e] * DD);
        const float4* ur = (const float4*)(u + g_rel[e] * DD);
        #pragma unroll
        for (int k = 0; k < 16; k++) {
            float4 a = xr[k], w = ur[k];
            acc += a.x*w.x + a.y*w.y + a.z*w.z + a.w*w.w;
        }
        v = __expf(acc);
        g_logit[e] = v;
    }
    smr[threadIdx.x] = v; __syncthreads();
    for (int s = 128; s > 0; s >>= 1) {
        if (threadIdx.x < s) smr[threadIdx.x] += smr[threadIdx.x + s];
        __syncthreads();
    }
    if (threadIdx.x == 0) atomicAdd(psum, smr[0]);
}

// ---------------- message scatter: aggr[dst] += x[src] * alpha (scalar atomics) -------
__global__ void k_scatter(const float* __restrict__ x, const int* __restrict__ src,
                          const int* __restrict__ dst, const float* __restrict__ psum)
{
    long idx = (long)blockIdx.x * 256 + threadIdx.x;
    if (idx >= (long)EE * DD) return;
    int e = (int)(idx >> 6), d = (int)(idx & 63);
    float a = g_logit[e] / *psum;
    atomicAdd(&g_aggr[(long)dst[e]*DD + d], x[(long)src[e]*DD + d] * a);
}

// ---------------- fused losses: kge (blocks < KB) + nt (rest) ----------------
#define KB 512
__global__ void k_loss(const int* __restrict__ src, const int* __restrict__ dst,
                       const float* __restrict__ rel_emb,
                       const int* __restrict__ labels,
                       const float* __restrict__ w_nt, const float* __restrict__ b_nt)
{
    __shared__ float smr[256];
    if (blockIdx.x < KB) {
        float acc = 0.f;
        for (long idx = (long)blockIdx.x * 256 + threadIdx.x; idx < (long)EE * 16;
             idx += (long)KB * 256) {
            int e = (int)(idx >> 4), q = (int)(idx & 15);
            if (g_mask[e] != 0.f) {
                float4 a = *(const float4*)&g_fx[(long)src[e]*DD + q*4];
                float4 b = *(const float4*)&g_fx[(long)dst[e]*DD + q*4];
                float4 r = *(const float4*)&rel_emb[g_rel[e]*DD + q*4];
                float dx = a.x + r.x - b.x;
                float dy = a.y + r.y - b.y;
                float dz = a.z + r.z - b.z;
                float dw = a.w + r.w - b.w;
                acc += dx*dx + dy*dy + dz*dz + dw*dw;
            }
        }
        smr[threadIdx.x] = acc; __syncthreads();
        for (int s = 128; s > 0; s >>= 1) {
            if (threadIdx.x < s) smr[threadIdx.x] += smr[threadIdx.x + s];
            __syncthreads();
        }
        if (threadIdx.x == 0) atomicAdd(&g_kge, smr[0]);
    } else {
        int n = (blockIdx.x - KB) * 256 + threadIdx.x;
        float loss = 0.f;
        if (n < MM) {
            const float* xr = g_fx + (long)n * DD;
            float z0 = b_nt[0], z1 = b_nt[1], z2 = b_nt[2];
            #pragma unroll 16
            for (int k = 0; k < DD; k++) {
                float v = xr[k];
                z0 += v * w_nt[k*3 + 0];
                z1 += v * w_nt[k*3 + 1];
                z2 += v * w_nt[k*3 + 2];
            }
            float mx  = fmaxf(z0, fmaxf(z1, z2));
            float lse = mx + logf(expf(z0 - mx) + expf(z1 - mx) + expf(z2 - mx));
            int lab = labels[n];
            float zl = (lab == 0) ? z0 : ((lab == 1) ? z1 : z2);
            loss = lse - zl;
        }
        smr[threadIdx.x] = loss; __syncthreads();
        for (int s = 128; s > 0; s >>= 1) {
            if (threadIdx.x < s) smr[threadIdx.x] += smr[threadIdx.x + s];
            __syncthreads();
        }
        if (threadIdx.x == 0) atomicAdd(&g_nt, smr[0]);
    }
}

// ---------------- write loss scalars ----------------
__global__ void k_finalize(float* __restrict__ out, long off)
{
    out[off]     = g_kge / (float)((long)EE * DD);
    out[off + 1] = g_nt / (float)MM;
}

// =====================================================================================
extern "C" void kernel_launch(void* const* d_in, const int* in_sizes, int n_in,
                              void* d_out, int out_size)
{
    const int*   node_ids   = (const int*)  d_in[0];
    const int*   edge_index = (const int*)  d_in[1];
    const float* edge_attr  = (const float*)d_in[2];
    const float* tokemb     = (const float*)d_in[3];
    const int*   labels     = (const int*)  d_in[4];
    const float* kg_emb     = (const float*)d_in[5];
    const float* rel_emb    = (const float*)d_in[6];
    const float* w_e2       = (const float*)d_in[7];
    const float* b_e2       = (const float*)d_in[8];
    const float* att1_w     = (const float*)d_in[9];
    const float* att1_b     = (const float*)d_in[10];
    const float* root1      = (const float*)d_in[11];
    const float* bias1      = (const float*)d_in[12];
    const float* att2_w     = (const float*)d_in[13];
    const float* att2_b     = (const float*)d_in[14];
    const float* root2      = (const float*)d_in[15];
    const float* bias2      = (const float*)d_in[16];
    const float* w_lin1     = (const float*)d_in[17];
    const float* b_lin1     = (const float*)d_in[18];
    const float* w_lin2     = (const float*)d_in[19];
    const float* b_lin2     = (const float*)d_in[20];
    const float* w_nt       = (const float*)d_in[21];
    const float* b_nt       = (const float*)d_in[22];
    float* out = (float*)d_out;

    const int* src = edge_index;        // edge_index[0, :]
    const int* dst = edge_index + EE;   // edge_index[1, :]

    void *px_, *ph_, *pfx_, *paggr_, *pu1_, *pu2_, *ps1_, *ps2_;
    cudaGetSymbolAddress(&px_,    g_x);
    cudaGetSymbolAddress(&ph_,    g_h);
    cudaGetSymbolAddress(&pfx_,   g_fx);
    cudaGetSymbolAddress(&paggr_, g_aggr);
    cudaGetSymbolAddress(&pu1_,   g_u1);
    cudaGetSymbolAddress(&pu2_,   g_u2);
    cudaGetSymbolAddress(&ps1_,   g_sum1);
    cudaGetSymbolAddress(&ps2_,   g_sum2);
    float* px    = (float*)px_;
    float* ph    = (float*)ph_;
    float* pfx   = (float*)pfx_;
    float* paggr = (float*)paggr_;
    float* pu1   = (float*)pu1_;
    float* pu2   = (float*)pu2_;
    float* ps1   = (float*)ps1_;
    float* ps2   = (float*)ps2_;

    // Streams/events created once on the (uncaptured) correctness call; reused in capture.
    static cudaStream_t s1 = nullptr, s2 = nullptr;
    static cudaEvent_t eFork, eJ1, eJ2, eFx, eLoss;
    if (!s1) {
        cudaStreamCreateWithFlags(&s1, cudaStreamNonBlocking);
        cudaStreamCreateWithFlags(&s2, cudaStreamNonBlocking);
        cudaEventCreateWithFlags(&eFork, cudaEventDisableTiming);
        cudaEventCreateWithFlags(&eJ1,   cudaEventDisableTiming);
        cudaEventCreateWithFlags(&eJ2,   cudaEventDisableTiming);
        cudaEventCreateWithFlags(&eFx,   cudaEventDisableTiming);
        cudaEventCreateWithFlags(&eLoss, cudaEventDisableTiming);
    }

    // ---- fork prep phase across 3 streams ----
    cudaEventRecord(eFork, 0);
    cudaStreamWaitEvent(s1, eFork, 0);
    cudaStreamWaitEvent(s2, eFork, 0);

    // s0: zero aggr + gather kg nodes + scalars; edge relation ids/mask
    k_init<<<(MM*16 + 255)/256, 256>>>(node_ids, kg_emb);
    k_relmask<<<EB, 256>>>(edge_attr);

    // s1: zero tok region, then token GEMM (split-K atomic into px)
    k_zerotok<<<(TT*16 + 255)/256, 256, 0, s1>>>();
    {
        dim3 grid(1, (TT + 127)/128, 8);
        gemm_f2<0,0,1,0><<<grid, 256, 0, s1>>>(tokemb, w_lin1, b_lin1, nullptr,
                                               px, TT, DD, TOKN, 96);
    }

    // s2: w_lin2 split + fused u-tables
    k_wsplit<<<(TOKN*DD + 255)/256, 256, 0, s2>>>(w_lin2);
    k_ufused<<<DD, 256, 0, s2>>>(rel_emb, w_e2, b_e2, att1_w, att2_w);

    // ---- join ----
    cudaEventRecord(eJ1, s1);
    cudaEventRecord(eJ2, s2);
    cudaStreamWaitEvent(0, eJ1, 0);
    cudaStreamWaitEvent(0, eJ2, 0);

    // ---- layer 1: x -> h (relu); gemm re-zeroes aggr for layer 2 ----
    k_p<<<(MM + 255)/256, 256>>>(px, att1_w, att1_b);
    k_logitexp<<<(EE + 255)/256, 256>>>(px, pu1, src, dst, ps1);
    k_scatter<<<(int)(((long)EE*DD + 255)/256), 256>>>(px, src, dst, ps1);
    {
        dim3 grid(1, (MM + 127)/128, 1);
        gemm_f2<1,1,0,1><<<grid, 256>>>(px, root1, bias1, paggr, ph, MM, DD, DD, DD);
    }

    // ---- layer 2: h -> final_x ----
    k_p<<<(MM + 255)/256, 256>>>(ph, att2_w, att2_b);
    k_logitexp<<<(EE + 255)/256, 256>>>(ph, pu2, src, dst, ps2);
    k_scatter<<<(int)(((long)EE*DD + 255)/256), 256>>>(ph, src, dst, ps2);
    {
        dim3 grid(1, (MM + 127)/128, 1);
        gemm_f2<0,1,0,0><<<grid, 256>>>(ph, root2, bias2, paggr, pfx, MM, DD, DD, DD);
    }

    // ---- fork tail: losses on s1, final GEMM on s0 (disjoint out regions) ----
    cudaEventRecord(eFx, 0);
    cudaStreamWaitEvent(s1, eFx, 0);
    k_loss<<<KB + (MM + 255)/256, 256, 0, s1>>>(src, dst, rel_emb, labels, w_nt, b_nt);
    k_finalize<<<1, 1, 0, s1>>>(out, (long)out_size - 2);

    {
        dim3 grid(TOKN/64, (MM + 127)/128, 1);
        k_gemm_mma<<<grid, 256>>>(pfx, b_lin2, out);
    }

    cudaEventRecord(eLoss, s1);
    cudaStreamWaitEvent(0, eLoss, 0);
}